// round 14
// baseline (speedup 1.0000x reference)
#include <cuda_runtime.h>
#include <math.h>

#define RE_D   6378.137
#define MU_D   398600.5
#define TWOPI_F 6.28318530717958647692f
#define INV_TWOPI_F 0.15915494309189533577f

#define XKE_F   ((float)(60.0 / sqrt(RE_D * RE_D * RE_D / MU_D)))
#define XKEI_F  ((float)(sqrt(RE_D * RE_D * RE_D / MU_D) / 60.0))
#define RE_F    ((float)RE_D)
#define J2_F    0.00108262998905f
#define J4_F    (-0.00000161098761f)
#define J3OJ2_F ((float)(-0.00000253215306 / 0.00108262998905))
#define X2O3_F  ((float)(2.0 / 3.0))
#define SS_F    ((float)(78.0 / RE_D + 1.0))
#define QZMS2T_F ((float)(((120.0 - 78.0) / RE_D) * ((120.0 - 78.0) / RE_D) \
                        * ((120.0 - 78.0) / RE_D) * ((120.0 - 78.0) / RE_D)))
#define VKPS_F  ((float)(RE_D * (60.0 / sqrt(RE_D * RE_D * RE_D / MU_D)) / 60.0))

// ---------------- packed f32x2: 2 satellites per thread ----------------
struct pf { unsigned long long v; };

__device__ __forceinline__ pf pk(float x, float y) {
    pf r; asm("mov.b64 %0,{%1,%2};" : "=l"(r.v) : "f"(x), "f"(y)); return r;
}
__device__ __forceinline__ float2 up(pf a) {
    float2 r; asm("mov.b64 {%0,%1},%2;" : "=f"(r.x), "=f"(r.y) : "l"(a.v)); return r;
}
__device__ __forceinline__ pf ps(float s) { return pk(s, s); }

__device__ __forceinline__ pf operator+(pf a, pf b) {
    pf r; asm("add.rn.f32x2 %0,%1,%2;" : "=l"(r.v) : "l"(a.v), "l"(b.v)); return r;
}
__device__ __forceinline__ pf operator*(pf a, pf b) {
    pf r; asm("mul.rn.f32x2 %0,%1,%2;" : "=l"(r.v) : "l"(a.v), "l"(b.v)); return r;
}
__device__ __forceinline__ pf pfma(pf a, pf b, pf c) {
    pf r; asm("fma.rn.f32x2 %0,%1,%2,%3;" : "=l"(r.v) : "l"(a.v), "l"(b.v), "l"(c.v)); return r;
}
__device__ __forceinline__ pf operator-(pf a, pf b) { return pfma(b, ps(-1.0f), a); }
__device__ __forceinline__ pf pneg(pf a) { return a * ps(-1.0f); }

// ---- scalar-per-half helpers (MUFU / floor not packable) ----
__device__ __forceinline__ float frcp(float x) { float r; asm("rcp.approx.f32 %0,%1;" : "=f"(r) : "f"(x)); return r; }
__device__ __forceinline__ float frsq(float x) { float r; asm("rsqrt.approx.f32 %0,%1;" : "=f"(r) : "f"(x)); return r; }

__device__ __forceinline__ pf prcp(pf a)  { float2 t = up(a); return pk(frcp(t.x), frcp(t.y)); }
__device__ __forceinline__ pf pdiv(pf a, pf b) { return a * prcp(b); }
__device__ __forceinline__ pf prsqrt(pf a){ float2 t = up(a); return pk(frsq(t.x), frsq(t.y)); }
__device__ __forceinline__ pf pfloor(pf a){ float2 t = up(a); return pk(floorf(t.x), floorf(t.y)); }
__device__ __forceinline__ void psc(pf a, pf& s, pf& c) {
    float2 t = up(a); float s0, c0, s1, c1;
    __sincosf(t.x, &s0, &c0); __sincosf(t.y, &s1, &c1);
    s = pk(s0, s1); c = pk(c0, c1);
}
__device__ __forceinline__ pf pmod2pi(pf x) {
    pf q = pfloor(x * ps(INV_TWOPI_F));
    return pfma(q, ps(-TWOPI_F), x);
}

// Inclination trig: hybrid fast/Cody-Waite-Taylor (R13). Near pi the
// 1+cosio cancellation (divided into xlcof) gets effectively-correctly-
// rounded cos from delta = (PI_HI - inclo) + PI_LO + Taylor.
#define PI_HI_F 3.14159274101257324219f
#define PI_LO_F (-8.74227765734758577e-8f)
__device__ __forceinline__ void incl_trig(float inclo, float& s, float& c, float& d) {
    if (inclo > 3.1296f) {
        float dl = (PI_HI_F - inclo) + PI_LO_F;
        float d2s = dl * dl;
        s = dl * (1.0f - d2s * (1.0f / 6.0f) * (1.0f - d2s * 0.05f));
        float cd = 1.0f - 0.5f * d2s * (1.0f - d2s * (1.0f / 12.0f) * (1.0f - d2s * (1.0f / 30.0f)));
        c = -cd;
        float dd = 1.0f + c;
        d = (fabsf(dd) > 1.5e-12f) ? dd : 1.5e-12f;
    } else {
        __sincosf(inclo, &s, &c);
        d = 1.0f + c;
    }
}

// Specialization (R6/R9): input support -> isimp=false, sfour=SS,
// qzms24=QZMS2T, ecco>1e-4, eeta>3e-6; cc1<=2.9e-11 kills d2..d4,
// t3cof..t5cof, nodecf below f32 rounding; |per|<=6.5e-5; em>0.
// R14 additions (all with error bounds << 1e-3 budget):
//  - no_unk = n*(1-del+del^2-del^3)            (del<=1e-3, err 1e-12)
//  - d1, pinvsq from one rsqrt(omeosq)
//  - sin/cos(argpm) by Taylor rotation from argpo (|dw|<=0.25, err 1.2e-8)
//  - betal, 1/(1+betal), 1/pl, tinv by series in el2/em^2 (<=5e-4)

__global__ void __launch_bounds__(256)
sgp4_kernel(const float* __restrict__ P,   // (N,7)
            const float* __restrict__ T,   // (N,)
            float* __restrict__ out,       // pos(3N) then vel(3N)
            int N)
{
    int ip = blockIdx.x * blockDim.x + threadIdx.x;   // pair index
    int s0 = 2 * ip;
    if (s0 >= N) return;
    bool has2 = (s0 + 1 < N);

    // -------- loads --------
    float a[14];
    float t0v, t1v;
    if (has2) {
        const float2* q = reinterpret_cast<const float2*>(P + 14 * (size_t)ip);
#pragma unroll
        for (int k = 0; k < 7; k++) { float2 w = q[k]; a[2 * k] = w.x; a[2 * k + 1] = w.y; }
        float2 tt = *reinterpret_cast<const float2*>(T + 2 * (size_t)ip);
        t0v = tt.x; t1v = tt.y;
    } else {
#pragma unroll
        for (int k = 0; k < 7; k++) { a[k] = P[7 * (size_t)s0 + k]; }
#pragma unroll
        for (int k = 0; k < 7; k++) { a[7 + k] = a[k]; }
        t0v = T[s0]; t1v = t0v;
    }

    pf ecco  = pk(a[1], a[8]);
    pf inclo = pk(a[2], a[9]);
    pf bstar = pk(a[6], a[13]);
    pf t     = pk(t0v, t1v);
    pf t2 = t * t;

    // ---------------- core orbit constants ----------------
    pf omeosq = ps(1.0f) - ecco * ecco;
    pf rs2    = prsqrt(omeosq);            // omeosq^-1/2
    pf rteosq = omeosq * rs2;              // sqrt(omeosq)
    pf rome   = rs2 * rs2;                 // 1/omeosq

    float si0, ci0, dn0, si1, ci1, dn1;
    incl_trig(a[2], si0, ci0, dn0);
    incl_trig(a[9], si1, ci1, dn1);
    pf sinio = pk(si0, si1);
    pf cosio = pk(ci0, ci1);
    pf denom = pk(dn0, dn1);
    pf cosio2 = cosio * cosio;

    float ak0 = __powf(__fdividef(XKE_F, a[0]), X2O3_F);
    float ak1 = __powf(__fdividef(XKE_F, a[7]), X2O3_F);
    pf ak = pk(ak0, ak1);
    pf n_koz = pk(a[0], a[7]);

    // d1 = 0.75*J2*(3c^2-1) * omeosq^-1.5
    pf d1 = ps(0.75f * J2_F) * pfma(ps(3.0f), cosio2, ps(-1.0f)) * (rome * rs2);
    pf del1 = pdiv(d1, ak * ak);
    pf dl1sq = del1 * del1;
    pf adel = ak * (ps(1.0f) - dl1sq - del1 * ps(1.0f / 3.0f));
    pf del_ = pdiv(d1, adel * adel);
    pf dsq = del_ * del_;
    // no_unk = n/(1+del) = n*(1-del+del^2-del^3), err ~1e-12
    pf no_unk = n_koz * (ps(1.0f) - del_ + dsq - dsq * del_);
    pf ao = ak * (ps(1.0f) + ps(X2O3_F) * del_ + ps(-1.0f / 9.0f) * dsq);

    pf con42 = pfma(ps(-5.0f), cosio2, ps(1.0f));
    pf con41 = pfma(ps(-2.0f), cosio2, pneg(con42));
    pf rao    = prcp(ao);
    pf rpo    = rao * rome;                // 1/po
    pf pinvsq = rpo * rpo;
    pf tsi    = prcp(ao - ps(SS_F));
    pf eta    = ao * ecco * tsi;
    pf etasq  = eta * eta;
    pf eeta   = ecco * eta;
    pf psisq  = ps(1.0f) - etasq;
    pf rs     = prsqrt(psisq);
    pf rpsi   = rs * rs;
    pf tsi2   = tsi * tsi;
    pf coef   = ps(QZMS2T_F) * (tsi2 * tsi2);
    pf coef1  = coef * (rpsi * rpsi) * (rpsi * rs);
    pf x1mth2 = ps(1.0f) - cosio2;
    pf cosio4 = cosio2 * cosio2;

    pf jtsips = ps(J2_F) * tsi * rpsi;
    pf cc2 = coef1 * no_unk * (ao * (ps(1.0f) + ps(1.5f) * etasq + eeta * (ps(4.0f) + etasq))
           + ps(0.375f) * jtsips * con41 * (ps(8.0f) + ps(3.0f) * etasq * (ps(8.0f) + etasq)));
    pf cc1 = bstar * cc2;

    // ---- secular rates ----
    pf temp1 = ps(1.5f * J2_F) * pinvsq * no_unk;
    pf temp2 = ps(0.5f) * temp1 * ps(J2_F) * pinvsq;
    pf temp3 = ps(-0.46875f * J4_F) * pinvsq * pinvsq * no_unk;
    pf mdot = no_unk + ps(0.5f) * temp1 * rteosq * con41
            + ps(0.0625f) * temp2 * rteosq *
              (ps(13.0f) + ps(-78.0f) * cosio2 + ps(137.0f) * cosio4);
    pf argpdot = ps(-0.5f) * temp1 * con42
               + ps(0.0625f) * temp2 * (ps(7.0f) + ps(-114.0f) * cosio2 + ps(395.0f) * cosio4)
               + temp3 * (ps(3.0f) + ps(-36.0f) * cosio2 + ps(49.0f) * cosio4);
    pf xhdot1 = pneg(temp1 * cosio);
    pf nodedot = xhdot1 + (ps(0.5f) * temp2 * (ps(4.0f) + ps(-19.0f) * cosio2)
               + ps(2.0f) * temp3 * (ps(3.0f) + ps(-7.0f) * cosio2)) * cosio;

    pf mo    = pk(a[5], a[12]);
    pf argpo = pk(a[4], a[11]);
    pf xmdf  = pfma(mdot, t, mo);
    pf nodem = pfma(nodedot, t, pk(a[3], a[10]));

    // ---- periodic drag terms (|per| <= 6.5e-5) ----
    pf s_o, c_o;
    psc(argpo, s_o, c_o);                  // sin/cos(argpo)
    pf cc3 = pdiv(ps(-2.0f * J3OJ2_F) * coef * tsi * no_unk * sinio, ecco);
    pf sinmao, cosmo;
    psc(mo, sinmao, cosmo);
    pf s_x, c_x;
    psc(xmdf, s_x, c_x);
    pf dmo = pfma(eta, cosmo, ps(1.0f));
    pf cx  = pfma(eta, c_x, ps(1.0f));
    pf per = bstar * cc3 * c_o * t
           + pdiv(ps(-X2O3_F) * coef * bstar, eeta)
             * (cx * cx * cx - dmo * dmo * dmo);
    pf mm = xmdf + per;
    pf dw = argpdot * t - per;             // argpm - argpo, |dw| <= ~0.25
    pf argpm = argpo + dw;
    pf sin_mm = pfma(c_x, per, s_x);

    // ---- tempe ----
    pf cos2argpo = pfma(ps(2.0f) * c_o, c_o, ps(-1.0f));
    pf cc4 = ps(2.0f) * no_unk * coef1 * ao * omeosq * (
          eta * (ps(2.0f) + ps(0.5f) * etasq) + ecco * (ps(0.5f) + ps(2.0f) * etasq)
        - (jtsips * rao) * (ps(-3.0f) * con41 *
              (ps(1.0f) - ps(2.0f) * eeta + etasq * (ps(1.5f) - ps(0.5f) * eeta))
            + ps(0.75f) * x1mth2 * (ps(2.0f) * etasq - eeta * (ps(1.0f) + etasq)) * cos2argpo));
    pf cc5 = ps(2.0f) * coef1 * ao * omeosq * (ps(1.0f) + ps(2.75f) * (etasq + eeta) + eeta * etasq);
    pf em = ecco - (bstar * cc4 * t + bstar * cc5 * (sin_mm - sinmao));

    pf tempa = ps(1.0f) - cc1 * t;
    pf templ = ps(1.5f) * cc1 * t2;

    pf am = ao * tempa * tempa;
    pf rsam = prsqrt(am);
    pf sqam = am * rsam;
    pf ram = rsam * rsam;                  // 1/am
    pf nm = ps(XKE_F) * (rsam * rsam * rsam);
    mm = pfma(no_unk, templ, mm);
    pf xlm = pmod2pi(mm + argpm + nodem);

    // sin/cos(argpm) = rotate sin/cos(argpo) by dw (Taylor 5th/6th, err<=1.2e-8)
    pf dw2 = dw * dw;
    pf sdw = dw * (ps(1.0f) - dw2 * ps(1.0f / 6.0f) * (ps(1.0f) - dw2 * ps(0.05f)));
    pf cdw = ps(1.0f) - ps(0.5f) * dw2 * (ps(1.0f) - dw2 * ps(1.0f / 12.0f) * (ps(1.0f) - dw2 * ps(1.0f / 30.0f)));
    pf sargpm = pfma(s_o, cdw, c_o * sdw);
    pf cargpm = c_o * cdw - s_o * sdw;

    pf axnl = em * cargpm;
    pf emsq = em * em;                     // <= 4.8e-4
    // tinv = 1/(am*(1-em^2)) = ram*(1+em^2+em^4), err ~1e-10
    pf tinv = ram * (ps(1.0f) + emsq + emsq * emsq);
    pf aycof = ps(-0.5f * J3OJ2_F) * sinio;
    pf xlcof = pdiv(ps(-0.25f * J3OJ2_F) * sinio * pfma(ps(5.0f), cosio, ps(3.0f)), denom);
    pf aynl = pfma(tinv, aycof, em * sargpm);
    pf u = (xlm - nodem) + tinv * xlcof * axnl;

    // ---- Kepler: one sincos + 2 analytic Newton steps, one rcp ----
    pf s_u, c_u;
    psc(u, s_u, c_u);
    pf num0 = axnl * s_u - aynl * c_u;
    pf rden = prcp(ps(1.0f) - axnl * c_u - aynl * s_u);
    pf dd1 = num0 * rden;
    pf dd1sq = dd1 * dd1;
    pf sind = dd1 * (ps(1.0f) - dd1sq * ps(1.0f / 6.0f));
    pf cosd = ps(1.0f) - ps(0.5f) * dd1sq + ps(1.0f / 24.0f) * (dd1sq * dd1sq);
    pf sE1 = pfma(s_u, cosd, c_u * sind);
    pf cE1 = c_u * cosd - s_u * sind;
    pf num1 = (axnl * sE1 - aynl * cE1) - dd1;
    pf dd2 = num1 * rden;
    pf sineo1 = pfma(cE1, dd2, sE1);
    pf coseo1 = cE1 - sE1 * dd2;

    pf ecose = pfma(axnl, coseo1, aynl * sineo1);
    pf esine = axnl * sineo1 - aynl * coseo1;
    pf el2 = pfma(axnl, axnl, aynl * aynl);        // <= 5e-4
    pf rl = am * (ps(1.0f) - ecose);
    pf rlinv = prcp(rl);
    // betal = sqrt(1-el2) by series, err ~2e-15
    pf betal = ps(1.0f) - el2 * (ps(0.5f) + el2 * (ps(0.125f) + el2 * ps(0.0625f)));
    pf rdotl  = sqam * esine * rlinv;
    pf rvdotl = sqam * betal * rlinv;
    // tq = esine/(1+betal): 1/(1+betal) = 0.5*(1+q+q^2), q = el2/4+el2^2/16
    pf qq = el2 * (ps(0.25f) + el2 * ps(0.0625f));
    pf tq = esine * ps(0.5f) * (ps(1.0f) + qq + qq * qq);
    pf amorl = am * rlinv;
    pf sn = amorl * ((sineo1 - aynl) - axnl * tq);
    pf cn = amorl * ((coseo1 - axnl) + aynl * tq);
    pf sin2u = ps(2.0f) * cn * sn;
    pf cos2u = ps(1.0f) - ps(2.0f) * sn * sn;
    // pli = 1/pl = ram*(1+el2+el2^2+el2^3), err ~6e-14
    pf pli = ram * (ps(1.0f) + el2 * (ps(1.0f) + el2 * (ps(1.0f) + el2)));
    pf tb = ps(0.5f * J2_F) * pli;
    pf tc = tb * pli;

    pf mrt = rl * (ps(1.0f) - ps(1.5f) * tc * betal * con41) + ps(0.5f) * tb * x1mth2 * cos2u;
    pf x7thm1 = pfma(ps(7.0f), cosio2, ps(-1.0f));
    pf corr = ps(0.25f) * tc * x7thm1 * sin2u;
    pf ccor = ps(1.0f) - ps(0.5f) * corr * corr;
    pf sinsu = sn * ccor - cn * corr;
    pf cossu = pfma(sn, corr, cn * ccor);

    pf xnode = pfma(ps(1.5f) * tc * cosio, sin2u, nodem);
    pf mvt   = rdotl - nm * tb * x1mth2 * sin2u * ps(XKEI_F);
    pf rvdot = rvdotl + nm * tb * pfma(x1mth2, cos2u, ps(1.5f) * con41) * ps(XKEI_F);

    pf snod, cnod; psc(xnode, snod, cnod);
    pf di = ps(1.5f) * tc * cosio * sinio * cos2u;
    pf cdi = ps(1.0f) - ps(0.5f) * di * di;
    pf sini = pfma(cosio, di, sinio * cdi);
    pf cosi = cosio * cdi - sinio * di;

    pf xmx = pneg(snod) * cosi;
    pf xmy = cnod * cosi;
    pf ux = pfma(xmx, sinsu, cnod * cossu);
    pf uy = pfma(xmy, sinsu, snod * cossu);
    pf uz = sini * sinsu;
    pf vx = xmx * cossu - cnod * sinsu;
    pf vy = xmy * cossu - snod * sinsu;
    pf vz = sini * cossu;

    pf mr = mrt * ps(RE_F);
    pf PX = mr * ux;
    pf PY = mr * uy;
    pf PZ = mr * uz;
    pf VX = ps(VKPS_F) * pfma(mvt, ux, rvdot * vx);
    pf VY = ps(VKPS_F) * pfma(mvt, uy, rvdot * vy);
    pf VZ = ps(VKPS_F) * pfma(mvt, uz, rvdot * vz);

    float2 px = up(PX), py = up(PY), pz = up(PZ);
    float2 vxx = up(VX), vyy = up(VY), vzz = up(VZ);

    float* pos = out;
    float* vel = out + 3 * (size_t)N;
    size_t base = 6 * (size_t)ip;
    if (has2) {
        *reinterpret_cast<float2*>(pos + base + 0) = make_float2(px.x, py.x);
        *reinterpret_cast<float2*>(pos + base + 2) = make_float2(pz.x, px.y);
        *reinterpret_cast<float2*>(pos + base + 4) = make_float2(py.y, pz.y);
        *reinterpret_cast<float2*>(vel + base + 0) = make_float2(vxx.x, vyy.x);
        *reinterpret_cast<float2*>(vel + base + 2) = make_float2(vzz.x, vxx.y);
        *reinterpret_cast<float2*>(vel + base + 4) = make_float2(vyy.y, vzz.y);
    } else {
        pos[base + 0] = px.x; pos[base + 1] = py.x; pos[base + 2] = pz.x;
        vel[base + 0] = vxx.x; vel[base + 1] = vyy.x; vel[base + 2] = vzz.x;
    }
}

extern "C" void kernel_launch(void* const* d_in, const int* in_sizes, int n_in,
                              void* d_out, int out_size) {
    const float* params = (const float*)d_in[0];   // (N,7) float32
    const float* tmin   = (const float*)d_in[1];   // (N,)  float32
    float* out = (float*)d_out;                    // pos(3N) | vel(3N)
    int N = in_sizes[1];
    int pairs = (N + 1) / 2;
    int threads = 256;
    int blocks = (pairs + threads - 1) / threads;
    sgp4_kernel<<<blocks, threads>>>(params, tmin, out, N);
}

// round 15
// speedup vs baseline: 1.0167x; 1.0167x over previous
#include <cuda_runtime.h>
#include <math.h>

#define RE_D   6378.137
#define MU_D   398600.5
#define TWOPI_F 6.28318530717958647692f
#define INV_TWOPI_F 0.15915494309189533577f

#define XKE_F   ((float)(60.0 / sqrt(RE_D * RE_D * RE_D / MU_D)))
#define XKEI_F  ((float)(sqrt(RE_D * RE_D * RE_D / MU_D) / 60.0))
#define RE_F    ((float)RE_D)
#define J2_F    0.00108262998905f
#define J4_F    (-0.00000161098761f)
#define J3OJ2_F ((float)(-0.00000253215306 / 0.00108262998905))
#define X2O3_F  ((float)(2.0 / 3.0))
#define SS_F    ((float)(78.0 / RE_D + 1.0))
#define QZMS2T_F ((float)(((120.0 - 78.0) / RE_D) * ((120.0 - 78.0) / RE_D) \
                        * ((120.0 - 78.0) / RE_D) * ((120.0 - 78.0) / RE_D)))
#define VKPS_F  ((float)(RE_D * (60.0 / sqrt(RE_D * RE_D * RE_D / MU_D)) / 60.0))

// ---------------- packed f32x2: 2 satellites per thread ----------------
struct pf { unsigned long long v; };

__device__ __forceinline__ pf pk(float x, float y) {
    pf r; asm("mov.b64 %0,{%1,%2};" : "=l"(r.v) : "f"(x), "f"(y)); return r;
}
__device__ __forceinline__ float2 up(pf a) {
    float2 r; asm("mov.b64 {%0,%1},%2;" : "=f"(r.x), "=f"(r.y) : "l"(a.v)); return r;
}
__device__ __forceinline__ pf ps(float s) { return pk(s, s); }

__device__ __forceinline__ pf operator+(pf a, pf b) {
    pf r; asm("add.rn.f32x2 %0,%1,%2;" : "=l"(r.v) : "l"(a.v), "l"(b.v)); return r;
}
__device__ __forceinline__ pf operator*(pf a, pf b) {
    pf r; asm("mul.rn.f32x2 %0,%1,%2;" : "=l"(r.v) : "l"(a.v), "l"(b.v)); return r;
}
__device__ __forceinline__ pf pfma(pf a, pf b, pf c) {
    pf r; asm("fma.rn.f32x2 %0,%1,%2,%3;" : "=l"(r.v) : "l"(a.v), "l"(b.v), "l"(c.v)); return r;
}
__device__ __forceinline__ pf operator-(pf a, pf b) { return pfma(b, ps(-1.0f), a); }
__device__ __forceinline__ pf pneg(pf a) { return a * ps(-1.0f); }

// ---- scalar-per-half helpers (MUFU / floor not packable) ----
__device__ __forceinline__ float frcp(float x) { float r; asm("rcp.approx.f32 %0,%1;" : "=f"(r) : "f"(x)); return r; }
__device__ __forceinline__ float frsq(float x) { float r; asm("rsqrt.approx.f32 %0,%1;" : "=f"(r) : "f"(x)); return r; }

__device__ __forceinline__ pf prcp(pf a)  { float2 t = up(a); return pk(frcp(t.x), frcp(t.y)); }
__device__ __forceinline__ pf pdiv(pf a, pf b) { return a * prcp(b); }
__device__ __forceinline__ pf prsqrt(pf a){ float2 t = up(a); return pk(frsq(t.x), frsq(t.y)); }
__device__ __forceinline__ pf pfloor(pf a){ float2 t = up(a); return pk(floorf(t.x), floorf(t.y)); }
__device__ __forceinline__ pf pcos(pf a)  { float2 t = up(a); return pk(__cosf(t.x), __cosf(t.y)); }
__device__ __forceinline__ void psc(pf a, pf& s, pf& c) {
    float2 t = up(a); float s0, c0, s1, c1;
    __sincosf(t.x, &s0, &c0); __sincosf(t.y, &s1, &c1);
    s = pk(s0, s1); c = pk(c0, c1);
}
__device__ __forceinline__ pf pmod2pi(pf x) {
    pf q = pfloor(x * ps(INV_TWOPI_F));
    return pfma(q, ps(-TWOPI_F), x);
}

// Inclination trig: hybrid fast/Cody-Waite-Taylor (R13). Near pi the
// 1+cosio cancellation (divided into xlcof) gets effectively-correctly-
// rounded cos from delta = (PI_HI - inclo) + PI_LO + Taylor.
#define PI_HI_F 3.14159274101257324219f
#define PI_LO_F (-8.74227765734758577e-8f)
__device__ __forceinline__ void incl_trig(float inclo, float& s, float& c, float& d) {
    if (inclo > 3.1296f) {
        float dl = (PI_HI_F - inclo) + PI_LO_F;
        float d2s = dl * dl;
        s = dl * (1.0f - d2s * (1.0f / 6.0f) * (1.0f - d2s * 0.05f));
        float cd = 1.0f - 0.5f * d2s * (1.0f - d2s * (1.0f / 12.0f) * (1.0f - d2s * (1.0f / 30.0f)));
        c = -cd;
        float dd = 1.0f + c;
        d = (fabsf(dd) > 1.5e-12f) ? dd : 1.5e-12f;
    } else {
        __sincosf(inclo, &s, &c);
        d = 1.0f + c;
    }
}

// Specialization (R6/R9/R13): input support -> isimp=false, sfour=SS,
// qzms24=QZMS2T, ecco>1e-4, eeta>3e-6; cc1<=2.9e-11 kills higher drag
// coeffs below f32 rounding; |per|<=6.5e-5; em>0.
// R15 series (short register lifetimes only):
//  - no_unk = n*(1-del+del^2-del^3)        (del<=1e-3, err 1e-12)
//  - d1/pinvsq/rteosq from one rsqrt(omeosq)
//  - betal, 1/(1+betal), 1/pl, tinv by series in el2/em^2 (<=5e-4)

__global__ void __launch_bounds__(256)
sgp4_kernel(const float* __restrict__ P,   // (N,7)
            const float* __restrict__ T,   // (N,)
            float* __restrict__ out,       // pos(3N) then vel(3N)
            int N)
{
    int ip = blockIdx.x * blockDim.x + threadIdx.x;   // pair index
    int s0 = 2 * ip;
    if (s0 >= N) return;
    bool has2 = (s0 + 1 < N);

    // -------- loads --------
    float a[14];
    float t0v, t1v;
    if (has2) {
        const float2* q = reinterpret_cast<const float2*>(P + 14 * (size_t)ip);
#pragma unroll
        for (int k = 0; k < 7; k++) { float2 w = q[k]; a[2 * k] = w.x; a[2 * k + 1] = w.y; }
        float2 tt = *reinterpret_cast<const float2*>(T + 2 * (size_t)ip);
        t0v = tt.x; t1v = tt.y;
    } else {
#pragma unroll
        for (int k = 0; k < 7; k++) { a[k] = P[7 * (size_t)s0 + k]; }
#pragma unroll
        for (int k = 0; k < 7; k++) { a[7 + k] = a[k]; }
        t0v = T[s0]; t1v = t0v;
    }

    pf ecco  = pk(a[1], a[8]);
    pf inclo = pk(a[2], a[9]);
    pf bstar = pk(a[6], a[13]);
    pf t     = pk(t0v, t1v);
    pf t2 = t * t;

    // ---------------- core orbit constants ----------------
    pf omeosq = ps(1.0f) - ecco * ecco;
    pf rs2    = prsqrt(omeosq);            // omeosq^-1/2
    pf rteosq = omeosq * rs2;              // sqrt(omeosq)
    pf rome   = rs2 * rs2;                 // 1/omeosq

    float si0, ci0, dn0, si1, ci1, dn1;
    incl_trig(a[2], si0, ci0, dn0);
    incl_trig(a[9], si1, ci1, dn1);
    pf sinio = pk(si0, si1);
    pf cosio = pk(ci0, ci1);
    pf denom = pk(dn0, dn1);
    pf cosio2 = cosio * cosio;

    float ak0 = __powf(__fdividef(XKE_F, a[0]), X2O3_F);
    float ak1 = __powf(__fdividef(XKE_F, a[7]), X2O3_F);
    pf ak = pk(ak0, ak1);
    pf n_koz = pk(a[0], a[7]);

    // d1 = 0.75*J2*(3c^2-1) * omeosq^-1.5
    pf d1 = ps(0.75f * J2_F) * pfma(ps(3.0f), cosio2, ps(-1.0f)) * (rome * rs2);
    pf del1 = pdiv(d1, ak * ak);
    pf dl1sq = del1 * del1;
    pf adel = ak * (ps(1.0f) - dl1sq - del1 * ps(1.0f / 3.0f));
    pf del_ = pdiv(d1, adel * adel);
    pf dsq = del_ * del_;
    // no_unk = n/(1+del) = n*(1-del+del^2-del^3), err ~1e-12
    pf no_unk = n_koz * (ps(1.0f) - del_ + dsq - dsq * del_);
    pf ao = ak * (ps(1.0f) + ps(X2O3_F) * del_ + ps(-1.0f / 9.0f) * dsq);

    pf con42 = pfma(ps(-5.0f), cosio2, ps(1.0f));
    pf con41 = pfma(ps(-2.0f), cosio2, pneg(con42));
    pf rao    = prcp(ao);
    pf rpo    = rao * rome;                // 1/po
    pf pinvsq = rpo * rpo;
    pf tsi    = prcp(ao - ps(SS_F));
    pf eta    = ao * ecco * tsi;
    pf etasq  = eta * eta;
    pf eeta   = ecco * eta;
    pf psisq  = ps(1.0f) - etasq;
    pf rs     = prsqrt(psisq);
    pf rpsi   = rs * rs;
    pf tsi2   = tsi * tsi;
    pf coef   = ps(QZMS2T_F) * (tsi2 * tsi2);
    pf coef1  = coef * (rpsi * rpsi) * (rpsi * rs);
    pf x1mth2 = ps(1.0f) - cosio2;
    pf cosio4 = cosio2 * cosio2;

    pf jtsips = ps(J2_F) * tsi * rpsi;
    pf cc2 = coef1 * no_unk * (ao * (ps(1.0f) + ps(1.5f) * etasq + eeta * (ps(4.0f) + etasq))
           + ps(0.375f) * jtsips * con41 * (ps(8.0f) + ps(3.0f) * etasq * (ps(8.0f) + etasq)));
    pf cc1 = bstar * cc2;

    // ---- secular rates ----
    pf temp1 = ps(1.5f * J2_F) * pinvsq * no_unk;
    pf temp2 = ps(0.5f) * temp1 * ps(J2_F) * pinvsq;
    pf temp3 = ps(-0.46875f * J4_F) * pinvsq * pinvsq * no_unk;
    pf mdot = no_unk + ps(0.5f) * temp1 * rteosq * con41
            + ps(0.0625f) * temp2 * rteosq *
              (ps(13.0f) + ps(-78.0f) * cosio2 + ps(137.0f) * cosio4);
    pf argpdot = ps(-0.5f) * temp1 * con42
               + ps(0.0625f) * temp2 * (ps(7.0f) + ps(-114.0f) * cosio2 + ps(395.0f) * cosio4)
               + temp3 * (ps(3.0f) + ps(-36.0f) * cosio2 + ps(49.0f) * cosio4);
    pf xhdot1 = pneg(temp1 * cosio);
    pf nodedot = xhdot1 + (ps(0.5f) * temp2 * (ps(4.0f) + ps(-19.0f) * cosio2)
               + ps(2.0f) * temp3 * (ps(3.0f) + ps(-7.0f) * cosio2)) * cosio;

    pf mo    = pk(a[5], a[12]);
    pf xmdf  = pfma(mdot, t, mo);
    pf argpm = pfma(argpdot, t, pk(a[4], a[11]));
    pf nodem = pfma(nodedot, t, pk(a[3], a[10]));

    // ---- periodic drag terms (|per| <= 6.5e-5) ----
    pf cosargpo = pcos(pk(a[4], a[11]));
    pf cc3 = pdiv(ps(-2.0f * J3OJ2_F) * coef * tsi * no_unk * sinio, ecco);
    pf sinmao, cosmo;
    psc(mo, sinmao, cosmo);
    pf s_x, c_x;
    psc(xmdf, s_x, c_x);
    pf dmo = pfma(eta, cosmo, ps(1.0f));
    pf cx  = pfma(eta, c_x, ps(1.0f));
    pf per = bstar * cc3 * cosargpo * t
           + pdiv(ps(-X2O3_F) * coef * bstar, eeta)
             * (cx * cx * cx - dmo * dmo * dmo);
    pf mm = xmdf + per;
    argpm = argpm - per;
    pf sin_mm = pfma(c_x, per, s_x);

    // ---- tempe ----
    pf cos2argpo = pfma(ps(2.0f) * cosargpo, cosargpo, ps(-1.0f));
    pf cc4 = ps(2.0f) * no_unk * coef1 * ao * omeosq * (
          eta * (ps(2.0f) + ps(0.5f) * etasq) + ecco * (ps(0.5f) + ps(2.0f) * etasq)
        - (jtsips * rao) * (ps(-3.0f) * con41 *
              (ps(1.0f) - ps(2.0f) * eeta + etasq * (ps(1.5f) - ps(0.5f) * eeta))
            + ps(0.75f) * x1mth2 * (ps(2.0f) * etasq - eeta * (ps(1.0f) + etasq)) * cos2argpo));
    pf cc5 = ps(2.0f) * coef1 * ao * omeosq * (ps(1.0f) + ps(2.75f) * (etasq + eeta) + eeta * etasq);
    pf em = ecco - (bstar * cc4 * t + bstar * cc5 * (sin_mm - sinmao));

    pf tempa = ps(1.0f) - cc1 * t;
    pf templ = ps(1.5f) * cc1 * t2;

    pf am = ao * tempa * tempa;
    pf rsam = prsqrt(am);
    pf sqam = am * rsam;
    pf ram = rsam * rsam;                  // 1/am
    pf nm = ps(XKE_F) * (rsam * rsam * rsam);
    mm = pfma(no_unk, templ, mm);
    pf xlm = pmod2pi(mm + argpm + nodem);

    pf sargpm, cargpm;
    psc(argpm, sargpm, cargpm);
    pf axnl = em * cargpm;
    pf emsq = em * em;                     // <= 4.8e-4
    // tinv = 1/(am*(1-em^2)) = ram*(1+em^2+em^4), err ~1e-10
    pf tinv = ram * (ps(1.0f) + emsq + emsq * emsq);
    pf aycof = ps(-0.5f * J3OJ2_F) * sinio;
    pf xlcof = pdiv(ps(-0.25f * J3OJ2_F) * sinio * pfma(ps(5.0f), cosio, ps(3.0f)), denom);
    pf aynl = pfma(tinv, aycof, em * sargpm);
    pf u = (xlm - nodem) + tinv * xlcof * axnl;

    // ---- Kepler: one sincos + 2 analytic Newton steps, one rcp ----
    pf s_u, c_u;
    psc(u, s_u, c_u);
    pf num0 = axnl * s_u - aynl * c_u;
    pf rden = prcp(ps(1.0f) - axnl * c_u - aynl * s_u);
    pf dd1 = num0 * rden;
    pf dd1sq = dd1 * dd1;
    pf sind = dd1 * (ps(1.0f) - dd1sq * ps(1.0f / 6.0f));
    pf cosd = ps(1.0f) - ps(0.5f) * dd1sq + ps(1.0f / 24.0f) * (dd1sq * dd1sq);
    pf sE1 = pfma(s_u, cosd, c_u * sind);
    pf cE1 = c_u * cosd - s_u * sind;
    pf num1 = (axnl * sE1 - aynl * cE1) - dd1;
    pf dd2 = num1 * rden;
    pf sineo1 = pfma(cE1, dd2, sE1);
    pf coseo1 = cE1 - sE1 * dd2;

    pf ecose = pfma(axnl, coseo1, aynl * sineo1);
    pf esine = axnl * sineo1 - aynl * coseo1;
    pf el2 = pfma(axnl, axnl, aynl * aynl);        // <= 5e-4
    pf rl = am * (ps(1.0f) - ecose);
    pf rlinv = prcp(rl);
    // betal = sqrt(1-el2) by series, err ~2e-15
    pf betal = ps(1.0f) - el2 * (ps(0.5f) + el2 * (ps(0.125f) + el2 * ps(0.0625f)));
    pf rdotl  = sqam * esine * rlinv;
    pf rvdotl = sqam * betal * rlinv;
    // tq = esine/(1+betal): 1/(1+betal) = 0.5*(1+q+q^2), q = el2/4+el2^2/16
    pf qq = el2 * (ps(0.25f) + el2 * ps(0.0625f));
    pf tq = esine * ps(0.5f) * (ps(1.0f) + qq + qq * qq);
    pf amorl = am * rlinv;
    pf sn = amorl * ((sineo1 - aynl) - axnl * tq);
    pf cn = amorl * ((coseo1 - axnl) + aynl * tq);
    pf sin2u = ps(2.0f) * cn * sn;
    pf cos2u = ps(1.0f) - ps(2.0f) * sn * sn;
    // pli = 1/pl = ram*(1+el2+el2^2+el2^3), err ~6e-14
    pf pli = ram * (ps(1.0f) + el2 * (ps(1.0f) + el2 * (ps(1.0f) + el2)));
    pf tb = ps(0.5f * J2_F) * pli;
    pf tc = tb * pli;

    pf mrt = rl * (ps(1.0f) - ps(1.5f) * tc * betal * con41) + ps(0.5f) * tb * x1mth2 * cos2u;
    pf x7thm1 = pfma(ps(7.0f), cosio2, ps(-1.0f));
    pf corr = ps(0.25f) * tc * x7thm1 * sin2u;
    pf ccor = ps(1.0f) - ps(0.5f) * corr * corr;
    pf sinsu = sn * ccor - cn * corr;
    pf cossu = pfma(sn, corr, cn * ccor);

    pf xnode = pfma(ps(1.5f) * tc * cosio, sin2u, nodem);
    pf mvt   = rdotl - nm * tb * x1mth2 * sin2u * ps(XKEI_F);
    pf rvdot = rvdotl + nm * tb * pfma(x1mth2, cos2u, ps(1.5f) * con41) * ps(XKEI_F);

    pf snod, cnod; psc(xnode, snod, cnod);
    pf di = ps(1.5f) * tc * cosio * sinio * cos2u;
    pf cdi = ps(1.0f) - ps(0.5f) * di * di;
    pf sini = pfma(cosio, di, sinio * cdi);
    pf cosi = cosio * cdi - sinio * di;

    pf xmx = pneg(snod) * cosi;
    pf xmy = cnod * cosi;
    pf ux = pfma(xmx, sinsu, cnod * cossu);
    pf uy = pfma(xmy, sinsu, snod * cossu);
    pf uz = sini * sinsu;
    pf vx = xmx * cossu - cnod * sinsu;
    pf vy = xmy * cossu - snod * sinsu;
    pf vz = sini * cossu;

    pf mr = mrt * ps(RE_F);
    pf PX = mr * ux;
    pf PY = mr * uy;
    pf PZ = mr * uz;
    pf VX = ps(VKPS_F) * pfma(mvt, ux, rvdot * vx);
    pf VY = ps(VKPS_F) * pfma(mvt, uy, rvdot * vy);
    pf VZ = ps(VKPS_F) * pfma(mvt, uz, rvdot * vz);

    float2 px = up(PX), py = up(PY), pz = up(PZ);
    float2 vxx = up(VX), vyy = up(VY), vzz = up(VZ);

    float* pos = out;
    float* vel = out + 3 * (size_t)N;
    size_t base = 6 * (size_t)ip;
    if (has2) {
        *reinterpret_cast<float2*>(pos + base + 0) = make_float2(px.x, py.x);
        *reinterpret_cast<float2*>(pos + base + 2) = make_float2(pz.x, px.y);
        *reinterpret_cast<float2*>(pos + base + 4) = make_float2(py.y, pz.y);
        *reinterpret_cast<float2*>(vel + base + 0) = make_float2(vxx.x, vyy.x);
        *reinterpret_cast<float2*>(vel + base + 2) = make_float2(vzz.x, vxx.y);
        *reinterpret_cast<float2*>(vel + base + 4) = make_float2(vyy.y, vzz.y);
    } else {
        pos[base + 0] = px.x; pos[base + 1] = py.x; pos[base + 2] = pz.x;
        vel[base + 0] = vxx.x; vel[base + 1] = vyy.x; vel[base + 2] = vzz.x;
    }
}

extern "C" void kernel_launch(void* const* d_in, const int* in_sizes, int n_in,
                              void* d_out, int out_size) {
    const float* params = (const float*)d_in[0];   // (N,7) float32
    const float* tmin   = (const float*)d_in[1];   // (N,)  float32
    float* out = (float*)d_out;                    // pos(3N) | vel(3N)
    int N = in_sizes[1];
    int pairs = (N + 1) / 2;
    int threads = 256;
    int blocks = (pairs + threads - 1) / threads;
    sgp4_kernel<<<blocks, threads>>>(params, tmin, out, N);
}

// round 16
// speedup vs baseline: 1.0304x; 1.0135x over previous
#include <cuda_runtime.h>
#include <math.h>

#define RE_D   6378.137
#define MU_D   398600.5
#define TWOPI_F 6.28318530717958647692f
#define INV_TWOPI_F 0.15915494309189533577f

#define XKE_F   ((float)(60.0 / sqrt(RE_D * RE_D * RE_D / MU_D)))
#define XKEI_F  ((float)(sqrt(RE_D * RE_D * RE_D / MU_D) / 60.0))
#define RE_F    ((float)RE_D)
#define J2_F    0.00108262998905f
#define J4_F    (-0.00000161098761f)
#define J3OJ2_F ((float)(-0.00000253215306 / 0.00108262998905))
#define X2O3_F  ((float)(2.0 / 3.0))
#define SS_F    ((float)(78.0 / RE_D + 1.0))
#define QZMS2T_F ((float)(((120.0 - 78.0) / RE_D) * ((120.0 - 78.0) / RE_D) \
                        * ((120.0 - 78.0) / RE_D) * ((120.0 - 78.0) / RE_D)))
#define VKPS_F  ((float)(RE_D * (60.0 / sqrt(RE_D * RE_D * RE_D / MU_D)) / 60.0))

// ---------------- packed f32x2: 2 satellites per thread ----------------
struct pf { unsigned long long v; };

__device__ __forceinline__ pf pk(float x, float y) {
    pf r; asm("mov.b64 %0,{%1,%2};" : "=l"(r.v) : "f"(x), "f"(y)); return r;
}
__device__ __forceinline__ float2 up(pf a) {
    float2 r; asm("mov.b64 {%0,%1},%2;" : "=f"(r.x), "=f"(r.y) : "l"(a.v)); return r;
}
__device__ __forceinline__ pf ps(float s) { return pk(s, s); }

__device__ __forceinline__ pf operator+(pf a, pf b) {
    pf r; asm("add.rn.f32x2 %0,%1,%2;" : "=l"(r.v) : "l"(a.v), "l"(b.v)); return r;
}
__device__ __forceinline__ pf operator*(pf a, pf b) {
    pf r; asm("mul.rn.f32x2 %0,%1,%2;" : "=l"(r.v) : "l"(a.v), "l"(b.v)); return r;
}
__device__ __forceinline__ pf pfma(pf a, pf b, pf c) {
    pf r; asm("fma.rn.f32x2 %0,%1,%2,%3;" : "=l"(r.v) : "l"(a.v), "l"(b.v), "l"(c.v)); return r;
}
__device__ __forceinline__ pf operator-(pf a, pf b) { return pfma(b, ps(-1.0f), a); }
__device__ __forceinline__ pf pneg(pf a) { return a * ps(-1.0f); }

// ---- scalar-per-half helpers (MUFU / floor not packable) ----
__device__ __forceinline__ float frcp(float x) { float r; asm("rcp.approx.f32 %0,%1;" : "=f"(r) : "f"(x)); return r; }
__device__ __forceinline__ float frsq(float x) { float r; asm("rsqrt.approx.f32 %0,%1;" : "=f"(r) : "f"(x)); return r; }

__device__ __forceinline__ pf prcp(pf a)  { float2 t = up(a); return pk(frcp(t.x), frcp(t.y)); }
__device__ __forceinline__ pf pdiv(pf a, pf b) { return a * prcp(b); }
__device__ __forceinline__ pf prsqrt(pf a){ float2 t = up(a); return pk(frsq(t.x), frsq(t.y)); }
__device__ __forceinline__ pf pfloor(pf a){ float2 t = up(a); return pk(floorf(t.x), floorf(t.y)); }
__device__ __forceinline__ pf pcos(pf a)  { float2 t = up(a); return pk(__cosf(t.x), __cosf(t.y)); }
__device__ __forceinline__ void psc(pf a, pf& s, pf& c) {
    float2 t = up(a); float s0, c0, s1, c1;
    __sincosf(t.x, &s0, &c0); __sincosf(t.y, &s1, &c1);
    s = pk(s0, s1); c = pk(c0, c1);
}
__device__ __forceinline__ pf pmod2pi(pf x) {
    pf q = pfloor(x * ps(INV_TWOPI_F));
    return pfma(q, ps(-TWOPI_F), x);
}

// Inclination trig: hybrid fast/Cody-Waite-Taylor (R13). Near pi the
// 1+cosio cancellation (divided into xlcof) gets effectively-correctly-
// rounded cos from delta = (PI_HI - inclo) + PI_LO + Taylor.
#define PI_HI_F 3.14159274101257324219f
#define PI_LO_F (-8.74227765734758577e-8f)
__device__ __forceinline__ void incl_trig(float inclo, float& s, float& c, float& d) {
    if (inclo > 3.1296f) {
        float dl = (PI_HI_F - inclo) + PI_LO_F;
        float d2s = dl * dl;
        s = dl * (1.0f - d2s * (1.0f / 6.0f) * (1.0f - d2s * 0.05f));
        float cd = 1.0f - 0.5f * d2s * (1.0f - d2s * (1.0f / 12.0f) * (1.0f - d2s * (1.0f / 30.0f)));
        c = -cd;
        float dd = 1.0f + c;
        d = (fabsf(dd) > 1.5e-12f) ? dd : 1.5e-12f;
    } else {
        __sincosf(inclo, &s, &c);
        d = 1.0f + c;
    }
}

// Specialization (R6/R9/R13/R15): input support -> isimp=false, sfour=SS,
// qzms24=QZMS2T, ecco>1e-4, eeta>3e-6; cc1<=2.9e-11 kills higher drag
// coeffs below f32 rounding; |per|<=6.5e-5; em>0.
// Series (short register lifetimes only): no_unk, betal, 1/(1+betal),
// 1/pl, tinv. R16: 1/eeta = recco^2 * rao * (ao-SS) (exact: 1/tsi = ao-SS).

__global__ void __launch_bounds__(256, 4)   // pin 64 regs -> 4 blocks/SM
sgp4_kernel(const float* __restrict__ P,   // (N,7)
            const float* __restrict__ T,   // (N,)
            float* __restrict__ out,       // pos(3N) then vel(3N)
            int N)
{
    int ip = blockIdx.x * blockDim.x + threadIdx.x;   // pair index
    int s0 = 2 * ip;
    if (s0 >= N) return;
    bool has2 = (s0 + 1 < N);

    // -------- loads --------
    float a[14];
    float t0v, t1v;
    if (has2) {
        const float2* q = reinterpret_cast<const float2*>(P + 14 * (size_t)ip);
#pragma unroll
        for (int k = 0; k < 7; k++) { float2 w = q[k]; a[2 * k] = w.x; a[2 * k + 1] = w.y; }
        float2 tt = *reinterpret_cast<const float2*>(T + 2 * (size_t)ip);
        t0v = tt.x; t1v = tt.y;
    } else {
#pragma unroll
        for (int k = 0; k < 7; k++) { a[k] = P[7 * (size_t)s0 + k]; }
#pragma unroll
        for (int k = 0; k < 7; k++) { a[7 + k] = a[k]; }
        t0v = T[s0]; t1v = t0v;
    }

    pf ecco  = pk(a[1], a[8]);
    pf inclo = pk(a[2], a[9]);
    pf bstar = pk(a[6], a[13]);
    pf t     = pk(t0v, t1v);
    pf t2 = t * t;

    // ---------------- core orbit constants ----------------
    pf omeosq = ps(1.0f) - ecco * ecco;
    pf rs2    = prsqrt(omeosq);            // omeosq^-1/2
    pf rteosq = omeosq * rs2;              // sqrt(omeosq)
    pf rome   = rs2 * rs2;                 // 1/omeosq

    float si0, ci0, dn0, si1, ci1, dn1;
    incl_trig(a[2], si0, ci0, dn0);
    incl_trig(a[9], si1, ci1, dn1);
    pf sinio = pk(si0, si1);
    pf cosio = pk(ci0, ci1);
    pf denom = pk(dn0, dn1);
    pf cosio2 = cosio * cosio;

    float ak0 = __powf(__fdividef(XKE_F, a[0]), X2O3_F);
    float ak1 = __powf(__fdividef(XKE_F, a[7]), X2O3_F);
    pf ak = pk(ak0, ak1);
    pf n_koz = pk(a[0], a[7]);

    // d1 = 0.75*J2*(3c^2-1) * omeosq^-1.5
    pf d1 = ps(0.75f * J2_F) * pfma(ps(3.0f), cosio2, ps(-1.0f)) * (rome * rs2);
    pf del1 = pdiv(d1, ak * ak);
    pf dl1sq = del1 * del1;
    pf adel = ak * (ps(1.0f) - dl1sq - del1 * ps(1.0f / 3.0f));
    pf del_ = pdiv(d1, adel * adel);
    pf dsq = del_ * del_;
    // no_unk = n/(1+del) = n*(1-del+del^2-del^3), err ~1e-12
    pf no_unk = n_koz * (ps(1.0f) - del_ + dsq - dsq * del_);
    pf ao = ak * (ps(1.0f) + ps(X2O3_F) * del_ + ps(-1.0f / 9.0f) * dsq);

    pf con42 = pfma(ps(-5.0f), cosio2, ps(1.0f));
    pf con41 = pfma(ps(-2.0f), cosio2, pneg(con42));
    pf rao    = prcp(ao);
    pf rpo    = rao * rome;                // 1/po
    pf pinvsq = rpo * rpo;
    pf aomss  = ao - ps(SS_F);             // = 1/tsi exactly
    pf tsi    = prcp(aomss);
    pf eta    = ao * ecco * tsi;
    pf etasq  = eta * eta;
    pf eeta   = ecco * eta;
    pf psisq  = ps(1.0f) - etasq;
    pf rs     = prsqrt(psisq);
    pf rpsi   = rs * rs;
    pf tsi2   = tsi * tsi;
    pf coef   = ps(QZMS2T_F) * (tsi2 * tsi2);
    pf coef1  = coef * (rpsi * rpsi) * (rpsi * rs);
    pf x1mth2 = ps(1.0f) - cosio2;
    pf cosio4 = cosio2 * cosio2;

    pf jtsips = ps(J2_F) * tsi * rpsi;
    pf cc2 = coef1 * no_unk * (ao * (ps(1.0f) + ps(1.5f) * etasq + eeta * (ps(4.0f) + etasq))
           + ps(0.375f) * jtsips * con41 * (ps(8.0f) + ps(3.0f) * etasq * (ps(8.0f) + etasq)));
    pf cc1 = bstar * cc2;

    // ---- secular rates ----
    pf temp1 = ps(1.5f * J2_F) * pinvsq * no_unk;
    pf temp2 = ps(0.5f) * temp1 * ps(J2_F) * pinvsq;
    pf temp3 = ps(-0.46875f * J4_F) * pinvsq * pinvsq * no_unk;
    pf mdot = no_unk + ps(0.5f) * temp1 * rteosq * con41
            + ps(0.0625f) * temp2 * rteosq *
              (ps(13.0f) + ps(-78.0f) * cosio2 + ps(137.0f) * cosio4);
    pf argpdot = ps(-0.5f) * temp1 * con42
               + ps(0.0625f) * temp2 * (ps(7.0f) + ps(-114.0f) * cosio2 + ps(395.0f) * cosio4)
               + temp3 * (ps(3.0f) + ps(-36.0f) * cosio2 + ps(49.0f) * cosio4);
    pf xhdot1 = pneg(temp1 * cosio);
    pf nodedot = xhdot1 + (ps(0.5f) * temp2 * (ps(4.0f) + ps(-19.0f) * cosio2)
               + ps(2.0f) * temp3 * (ps(3.0f) + ps(-7.0f) * cosio2)) * cosio;

    pf mo    = pk(a[5], a[12]);
    pf xmdf  = pfma(mdot, t, mo);
    pf argpm = pfma(argpdot, t, pk(a[4], a[11]));
    pf nodem = pfma(nodedot, t, pk(a[3], a[10]));

    // ---- periodic drag terms (|per| <= 6.5e-5) ----
    pf cosargpo = pcos(pk(a[4], a[11]));
    pf recco = prcp(ecco);                 // shared: cc3 and 1/eeta
    pf cc3 = ps(-2.0f * J3OJ2_F) * coef * tsi * no_unk * sinio * recco;
    // 1/eeta = 1/(ecco^2 * ao * tsi) = recco^2 * rao * (ao - SS)
    pf reeta = recco * recco * rao * aomss;
    pf sinmao, cosmo;
    psc(mo, sinmao, cosmo);
    pf s_x, c_x;
    psc(xmdf, s_x, c_x);
    pf dmo = pfma(eta, cosmo, ps(1.0f));
    pf cx  = pfma(eta, c_x, ps(1.0f));
    pf per = bstar * cc3 * cosargpo * t
           + ps(-X2O3_F) * coef * bstar * reeta
             * (cx * cx * cx - dmo * dmo * dmo);
    pf mm = xmdf + per;
    argpm = argpm - per;
    pf sin_mm = pfma(c_x, per, s_x);

    // ---- tempe ----
    pf cos2argpo = pfma(ps(2.0f) * cosargpo, cosargpo, ps(-1.0f));
    pf cc4 = ps(2.0f) * no_unk * coef1 * ao * omeosq * (
          eta * (ps(2.0f) + ps(0.5f) * etasq) + ecco * (ps(0.5f) + ps(2.0f) * etasq)
        - (jtsips * rao) * (ps(-3.0f) * con41 *
              (ps(1.0f) - ps(2.0f) * eeta + etasq * (ps(1.5f) - ps(0.5f) * eeta))
            + ps(0.75f) * x1mth2 * (ps(2.0f) * etasq - eeta * (ps(1.0f) + etasq)) * cos2argpo));
    pf cc5 = ps(2.0f) * coef1 * ao * omeosq * (ps(1.0f) + ps(2.75f) * (etasq + eeta) + eeta * etasq);
    pf em = ecco - (bstar * cc4 * t + bstar * cc5 * (sin_mm - sinmao));

    pf tempa = ps(1.0f) - cc1 * t;
    pf templ = ps(1.5f) * cc1 * t2;

    pf am = ao * tempa * tempa;
    pf rsam = prsqrt(am);
    pf sqam = am * rsam;
    pf ram = rsam * rsam;                  // 1/am
    pf nm = ps(XKE_F) * (rsam * rsam * rsam);
    mm = pfma(no_unk, templ, mm);
    pf xlm = pmod2pi(mm + argpm + nodem);

    pf sargpm, cargpm;
    psc(argpm, sargpm, cargpm);
    pf axnl = em * cargpm;
    pf emsq = em * em;                     // <= 4.8e-4
    // tinv = 1/(am*(1-em^2)) = ram*(1+em^2+em^4), err ~1e-10
    pf tinv = ram * (ps(1.0f) + emsq + emsq * emsq);
    pf aycof = ps(-0.5f * J3OJ2_F) * sinio;
    pf xlcof = pdiv(ps(-0.25f * J3OJ2_F) * sinio * pfma(ps(5.0f), cosio, ps(3.0f)), denom);
    pf aynl = pfma(tinv, aycof, em * sargpm);
    pf u = (xlm - nodem) + tinv * xlcof * axnl;

    // ---- Kepler: one sincos + 2 analytic Newton steps, one rcp ----
    pf s_u, c_u;
    psc(u, s_u, c_u);
    pf num0 = axnl * s_u - aynl * c_u;
    pf rden = prcp(ps(1.0f) - axnl * c_u - aynl * s_u);
    pf dd1 = num0 * rden;
    pf dd1sq = dd1 * dd1;
    pf sind = dd1 * (ps(1.0f) - dd1sq * ps(1.0f / 6.0f));
    pf cosd = ps(1.0f) - ps(0.5f) * dd1sq + ps(1.0f / 24.0f) * (dd1sq * dd1sq);
    pf sE1 = pfma(s_u, cosd, c_u * sind);
    pf cE1 = c_u * cosd - s_u * sind;
    pf num1 = (axnl * sE1 - aynl * cE1) - dd1;
    pf dd2 = num1 * rden;
    pf sineo1 = pfma(cE1, dd2, sE1);
    pf coseo1 = cE1 - sE1 * dd2;

    pf ecose = pfma(axnl, coseo1, aynl * sineo1);
    pf esine = axnl * sineo1 - aynl * coseo1;
    pf el2 = pfma(axnl, axnl, aynl * aynl);        // <= 5e-4
    pf rl = am * (ps(1.0f) - ecose);
    pf rlinv = prcp(rl);
    // betal = sqrt(1-el2) by series, err ~2e-15
    pf betal = ps(1.0f) - el2 * (ps(0.5f) + el2 * (ps(0.125f) + el2 * ps(0.0625f)));
    pf rdotl  = sqam * esine * rlinv;
    pf rvdotl = sqam * betal * rlinv;
    // tq = esine/(1+betal): 1/(1+betal) = 0.5*(1+q+q^2), q = el2/4+el2^2/16
    pf qq = el2 * (ps(0.25f) + el2 * ps(0.0625f));
    pf tq = esine * ps(0.5f) * (ps(1.0f) + qq + qq * qq);
    pf amorl = am * rlinv;
    pf sn = amorl * ((sineo1 - aynl) - axnl * tq);
    pf cn = amorl * ((coseo1 - axnl) + aynl * tq);
    pf sin2u = ps(2.0f) * cn * sn;
    pf cos2u = ps(1.0f) - ps(2.0f) * sn * sn;
    // pli = 1/pl = ram*(1+el2+el2^2+el2^3), err ~6e-14
    pf pli = ram * (ps(1.0f) + el2 * (ps(1.0f) + el2 * (ps(1.0f) + el2)));
    pf tb = ps(0.5f * J2_F) * pli;
    pf tc = tb * pli;

    pf mrt = rl * (ps(1.0f) - ps(1.5f) * tc * betal * con41) + ps(0.5f) * tb * x1mth2 * cos2u;
    pf x7thm1 = pfma(ps(7.0f), cosio2, ps(-1.0f));
    pf corr = ps(0.25f) * tc * x7thm1 * sin2u;
    pf ccor = ps(1.0f) - ps(0.5f) * corr * corr;
    pf sinsu = sn * ccor - cn * corr;
    pf cossu = pfma(sn, corr, cn * ccor);

    pf xnode = pfma(ps(1.5f) * tc * cosio, sin2u, nodem);
    pf mvt   = rdotl - nm * tb * x1mth2 * sin2u * ps(XKEI_F);
    pf rvdot = rvdotl + nm * tb * pfma(x1mth2, cos2u, ps(1.5f) * con41) * ps(XKEI_F);

    pf snod, cnod; psc(xnode, snod, cnod);
    pf di = ps(1.5f) * tc * cosio * sinio * cos2u;
    pf cdi = ps(1.0f) - ps(0.5f) * di * di;
    pf sini = pfma(cosio, di, sinio * cdi);
    pf cosi = cosio * cdi - sinio * di;

    pf xmx = pneg(snod) * cosi;
    pf xmy = cnod * cosi;
    pf ux = pfma(xmx, sinsu, cnod * cossu);
    pf uy = pfma(xmy, sinsu, snod * cossu);
    pf uz = sini * sinsu;
    pf vx = xmx * cossu - cnod * sinsu;
    pf vy = xmy * cossu - snod * sinsu;
    pf vz = sini * cossu;

    pf mr = mrt * ps(RE_F);
    pf PX = mr * ux;
    pf PY = mr * uy;
    pf PZ = mr * uz;
    pf VX = ps(VKPS_F) * pfma(mvt, ux, rvdot * vx);
    pf VY = ps(VKPS_F) * pfma(mvt, uy, rvdot * vy);
    pf VZ = ps(VKPS_F) * pfma(mvt, uz, rvdot * vz);

    float2 px = up(PX), py = up(PY), pz = up(PZ);
    float2 vxx = up(VX), vyy = up(VY), vzz = up(VZ);

    float* pos = out;
    float* vel = out + 3 * (size_t)N;
    size_t base = 6 * (size_t)ip;
    if (has2) {
        *reinterpret_cast<float2*>(pos + base + 0) = make_float2(px.x, py.x);
        *reinterpret_cast<float2*>(pos + base + 2) = make_float2(pz.x, px.y);
        *reinterpret_cast<float2*>(pos + base + 4) = make_float2(py.y, pz.y);
        *reinterpret_cast<float2*>(vel + base + 0) = make_float2(vxx.x, vyy.x);
        *reinterpret_cast<float2*>(vel + base + 2) = make_float2(vzz.x, vxx.y);
        *reinterpret_cast<float2*>(vel + base + 4) = make_float2(vyy.y, vzz.y);
    } else {
        pos[base + 0] = px.x; pos[base + 1] = py.x; pos[base + 2] = pz.x;
        vel[base + 0] = vxx.x; vel[base + 1] = vyy.x; vel[base + 2] = vzz.x;
    }
}

extern "C" void kernel_launch(void* const* d_in, const int* in_sizes, int n_in,
                              void* d_out, int out_size) {
    const float* params = (const float*)d_in[0];   // (N,7) float32
    const float* tmin   = (const float*)d_in[1];   // (N,)  float32
    float* out = (float*)d_out;                    // pos(3N) | vel(3N)
    int N = in_sizes[1];
    int pairs = (N + 1) / 2;
    int threads = 256;
    int blocks = (pairs + threads - 1) / threads;
    sgp4_kernel<<<blocks, threads>>>(params, tmin, out, N);
}